// round 10
// baseline (speedup 1.0000x reference)
#include <cuda_runtime.h>
#include <cuda.h>
#include <math.h>
#include <string.h>

// Problem constants (fixed shapes from setup_inputs)
#define NB 256
#define NJ 24
#define TDIM 1024
#define NF 8
// loss scale: 1 / (B * F * J * 3)
#define LOSS_SCALE (1.0f / 147456.0f)

// Per-block TMA staging: 16 boxes (2 sides x 8 frames), each 144 rows x 32B.
#define SLOT_BYTES  4608            // 144 * 32 (multiple of 128)
#define SLOT_FLOATS 1152
#define TILE_BYTES  (16 * SLOT_BYTES)   // 73728

// Ancestor path (root -> j, inclusive) per joint, padded; LEN = path length.
__device__ __constant__ int c_PATH[NJ][9] = {
    {0,0,0,0,0,0,0,0,0},          // 0
    {0,1,0,0,0,0,0,0,0},          // 1
    {0,2,0,0,0,0,0,0,0},          // 2
    {0,3,0,0,0,0,0,0,0},          // 3
    {0,1,4,0,0,0,0,0,0},          // 4
    {0,2,5,0,0,0,0,0,0},          // 5
    {0,3,6,0,0,0,0,0,0},          // 6
    {0,1,4,7,0,0,0,0,0},          // 7
    {0,2,5,8,0,0,0,0,0},          // 8
    {0,3,6,9,0,0,0,0,0},          // 9
    {0,1,4,7,10,0,0,0,0},         // 10
    {0,2,5,8,11,0,0,0,0},         // 11
    {0,3,6,9,12,0,0,0,0},         // 12
    {0,3,6,9,13,0,0,0,0},         // 13
    {0,3,6,9,14,0,0,0,0},         // 14
    {0,3,6,9,12,15,0,0,0},        // 15
    {0,3,6,9,13,16,0,0,0},        // 16
    {0,3,6,9,14,17,0,0,0},        // 17
    {0,3,6,9,13,16,18,0,0},       // 18
    {0,3,6,9,14,17,19,0,0},       // 19
    {0,3,6,9,13,16,18,20,0},      // 20
    {0,3,6,9,14,17,19,21,0},      // 21
    {0,3,6,9,13,16,18,20,22},     // 22
    {0,3,6,9,14,17,19,21,23}      // 23
};
__device__ __constant__ int c_LEN[NJ] = {
    1,2,2,2,3,3,3,4,4,4,5,5,5,5,5,6,6,6,7,7,8,8,9,9
};
// linspace(0, 1023, 8).astype(int32)
__device__ __constant__ int c_FIDX[NF] = {0,146,292,438,584,730,876,1023};
// Sector-aligned start (fi & ~7) and offset within the 8-float box.
__device__ __constant__ int c_T0 [NF] = {0,144,288,432,584,728,872,1016};
__device__ __constant__ int c_OFF[NF] = {0,2,4,6,0,2,4,7};

// Tensormaps in DEVICE GLOBAL memory, explicitly over-aligned (TMA requires
// 64B-aligned descriptors; the R8 param-space path faulted misaligned).
__device__ __align__(128) CUtensorMap g_tm[2];

// Device-global reduction state (zero-initialized at module load; each launch
// leaves it back at zero -> deterministic across graph replays).
__device__ float        g_acc = 0.0f;
__device__ unsigned int g_cnt = 0u;

struct Quat { float w, x, y, z; };

__device__ __forceinline__ float ld_plain(const float* p) {
    float v;
    asm("ld.global.f32 %0, [%1];" : "=f"(v) : "l"(p));
    return v;
}

__device__ __forceinline__ Quat qmul(const Quat a, const Quat b) {
    Quat r;
    r.w = a.w*b.w - a.x*b.x - a.y*b.y - a.z*b.z;
    r.x = a.w*b.x + a.x*b.w + a.y*b.z - a.z*b.y;
    r.y = a.w*b.y - a.x*b.z + a.y*b.w + a.z*b.x;
    r.z = a.w*b.z + a.x*b.y - a.y*b.x + a.z*b.w;
    return r;
}

__device__ __forceinline__ void qrot(const Quat q, float vx, float vy, float vz,
                                     float& ox, float& oy, float& oz) {
    float tx = 2.0f * (q.y*vz - q.z*vy);
    float ty = 2.0f * (q.z*vx - q.x*vz);
    float tz = 2.0f * (q.x*vy - q.y*vx);
    ox = vx + q.w*tx + (q.y*tz - q.z*ty);
    oy = vy + q.w*ty + (q.z*tx - q.x*tz);
    oz = vz + q.w*tz + (q.x*ty - q.y*tx);
}

__device__ __forceinline__ Quat quat_from_6d(const float v[6]) {
    float a1x = v[0], a1y = v[1], a1z = v[2];
    float a2x = v[3], a2y = v[4], a2z = v[5];
    float n1 = sqrtf(a1x*a1x + a1y*a1y + a1z*a1z);
    float i1 = 1.0f / fmaxf(n1, 1e-8f);
    float b1x = a1x*i1, b1y = a1y*i1, b1z = a1z*i1;
    float d = b1x*a2x + b1y*a2y + b1z*a2z;
    float ux = a2x - d*b1x, uy = a2y - d*b1y, uz = a2z - d*b1z;
    float n2 = sqrtf(ux*ux + uy*uy + uz*uz);
    float i2 = 1.0f / fmaxf(n2, 1e-8f);
    float b2x = ux*i2, b2y = uy*i2, b2z = uz*i2;
    float b3x = b1y*b2z - b1z*b2y;
    float b3y = b1z*b2x - b1x*b2z;
    float b3z = b1x*b2y - b1y*b2x;
    float m00 = b1x, m01 = b1y, m02 = b1z;
    float m10 = b2x, m11 = b2y, m12 = b2z;
    float m20 = b3x, m21 = b3y, m22 = b3z;

    float qa0 = sqrtf(fmaxf(1.0f + m00 + m11 + m22, 0.0f));
    float qa1 = sqrtf(fmaxf(1.0f + m00 - m11 - m22, 0.0f));
    float qa2 = sqrtf(fmaxf(1.0f - m00 + m11 - m22, 0.0f));
    float qa3 = sqrtf(fmaxf(1.0f - m00 - m11 + m22, 0.0f));

    int k = 0; float best = qa0;
    if (qa1 > best) { k = 1; best = qa1; }
    if (qa2 > best) { k = 2; best = qa2; }
    if (qa3 > best) { k = 3; best = qa3; }

    float w, x, y, z, qa;
    if (k == 0) { qa = qa0; w = qa0*qa0;  x = m21 - m12; y = m02 - m20; z = m10 - m01; }
    else if (k == 1) { qa = qa1; w = m21 - m12; x = qa1*qa1;  y = m10 + m01; z = m02 + m20; }
    else if (k == 2) { qa = qa2; w = m02 - m20; x = m10 + m01; y = qa2*qa2;  z = m12 + m21; }
    else             { qa = qa3; w = m10 - m01; x = m20 + m02; y = m21 + m12; z = qa3*qa3;  }

    float inv = 1.0f / (2.0f * fmaxf(qa, 0.1f));
    Quat q; q.w = w*inv; q.x = x*inv; q.y = y*inv; q.z = z*inv;
    return q;
}

// ---------------------------------------------------------------------------
// Shared phases 2/3 + grid reduction (identical FP order to reference).
// ---------------------------------------------------------------------------
__device__ __forceinline__ void fk_tail(
    float (*s_lq)[2][NJ][4], float (*s_gq)[2][NJ][4], float* s_part,
    int tid, int f, int s, int j,
    const float* __restrict__ offsets, float* __restrict__ out)
{
    // phase 2: global quats (left-fold along ancestor path)
    {
        Quat q = { s_lq[f][s][0][0], s_lq[f][s][0][1], s_lq[f][s][0][2], s_lq[f][s][0][3] };
        const int len = c_LEN[j];
        for (int d2 = 1; d2 < len; ++d2) {
            const int a = c_PATH[j][d2];
            Quat l = { s_lq[f][s][a][0], s_lq[f][s][a][1], s_lq[f][s][a][2], s_lq[f][s][a][3] };
            q = qmul(q, l);
        }
        s_gq[f][s][j][0] = q.w; s_gq[f][s][j][1] = q.x;
        s_gq[f][s][j][2] = q.y; s_gq[f][s][j][3] = q.z;
    }
    __syncthreads();

    // phase 3: position diff (root translation cancels; joint 0 contributes 0)
    float acc = 0.0f;
    if (s == 0) {
        float px = 0.f, py = 0.f, pz = 0.f;
        float tx2 = 0.f, ty2 = 0.f, tz2 = 0.f;
        const int len = c_LEN[j];
        for (int d2 = 1; d2 < len; ++d2) {
            const int a = c_PATH[j][d2];
            const int p = c_PATH[j][d2 - 1];
            const float ox = __ldg(offsets + a * 3 + 0);
            const float oy = __ldg(offsets + a * 3 + 1);
            const float oz = __ldg(offsets + a * 3 + 2);
            Quat qp = { s_gq[f][0][p][0], s_gq[f][0][p][1], s_gq[f][0][p][2], s_gq[f][0][p][3] };
            Quat qt = { s_gq[f][1][p][0], s_gq[f][1][p][1], s_gq[f][1][p][2], s_gq[f][1][p][3] };
            float rx, ry, rz;
            qrot(qp, ox, oy, oz, rx, ry, rz);  px  += rx; py  += ry; pz  += rz;
            qrot(qt, ox, oy, oz, rx, ry, rz);  tx2 += rx; ty2 += ry; tz2 += rz;
        }
        const float dx = px - tx2, dy = py - ty2, dz = pz - tz2;
        acc = dx*dx + dy*dy + dz*dz;
    }

    // block reduce
#pragma unroll
    for (int o = 16; o > 0; o >>= 1)
        acc += __shfl_down_sync(0xffffffffu, acc, o);
    const int wid  = tid >> 5;
    const int lane = tid & 31;
    if (lane == 0) s_part[wid] = acc;
    __syncthreads();

    // grid reduce: device-global accumulator; last block writes + resets
    if (tid == 0) {
        float total = 0.0f;
#pragma unroll
        for (int w = 0; w < 12; ++w) total += s_part[w];
        atomicAdd(&g_acc, total);
        __threadfence();
        unsigned int old = atomicAdd(&g_cnt, 1u);
        if (old == NB - 1u) {
            __threadfence();
            float tot = *((volatile float*)&g_acc);
            out[0] = tot * LOSS_SCALE;
            *((volatile float*)&g_acc) = 0.0f;
            __threadfence();
            *((volatile unsigned int*)&g_cnt) = 0u;
        }
    }
}

// ---------------------------------------------------------------------------
// TMA kernel: sector-granularity gather via tensormaps (device-global) with
// L2_PROMOTION_NONE. One block per batch b; 16 box loads (2 sides x 8 frames),
// each {8 floats, 144 jc-rows, 1}: exactly one 32B sector per (jc, f, side).
// ---------------------------------------------------------------------------
__global__ void __launch_bounds__(384, 2)
fk_loss_tma(const float* __restrict__ offsets,
            float* __restrict__ out)
{
    extern __shared__ __align__(128) float s_tile[];   // 16 * 1152 floats
    __shared__ __align__(8) unsigned long long s_mbar;
    __shared__ float s_lq[NF][2][NJ][4];
    __shared__ float s_gq[NF][2][NJ][4];
    __shared__ float s_part[12];

    const int tid = threadIdx.x;
    const int b   = blockIdx.x;
    const int f   = tid / 48;
    const int r   = tid - f * 48;
    const int s   = r / NJ;
    const int j   = r - s * NJ;

    uint32_t mbar;
    asm("{ .reg .u64 t; cvta.to.shared.u64 t, %1; cvt.u32.u64 %0, t; }"
        : "=r"(mbar) : "l"(&s_mbar));
    uint32_t tile_base;
    asm("{ .reg .u64 t; cvta.to.shared.u64 t, %1; cvt.u32.u64 %0, t; }"
        : "=r"(tile_base) : "l"(s_tile));

    if (tid == 0) {
        asm volatile("mbarrier.init.shared.b64 [%0], %1;" :: "r"(mbar), "r"(1u) : "memory");
    }
    __syncthreads();

    if (tid == 0) {
        asm volatile("mbarrier.arrive.expect_tx.shared.b64 _, [%0], %1;"
                     :: "r"(mbar), "r"((uint32_t)TILE_BYTES) : "memory");
    }
    // threads 0..15 each issue one box load: (side = tid>>3, frame = tid&7)
    if (tid < 16) {
        const int ss = tid >> 3;
        const int ff = tid & 7;
        const CUtensorMap* tm = &g_tm[ss];
        if (ff == 0) {
            asm volatile("prefetch.tensormap [%0];" :: "l"(tm));
        }
        uint32_t dst = tile_base + (uint32_t)((ss * 8 + ff) * SLOT_BYTES);
        asm volatile(
            "cp.async.bulk.tensor.3d.shared::cta.global.tile.mbarrier::complete_tx::bytes "
            "[%0], [%1, {%2, %3, %4}], [%5];"
            :: "r"(dst), "l"(tm),
               "r"(c_T0[ff]), "r"(0), "r"(b),
               "r"(mbar)
            : "memory");
    }

    // wait for all 16 boxes (73728 bytes) to land
    {
        uint32_t done;
        asm volatile(
            "{\n\t"
            ".reg .pred p;\n\t"
            "mbarrier.try_wait.parity.acquire.cta.shared::cta.b64 p, [%1], %2;\n\t"
            "selp.b32 %0, 1, 0, p;\n\t"
            "}"
            : "=r"(done) : "r"(mbar), "r"(0u) : "memory");
        if (!done) {
            asm volatile(
                "{\n\t"
                ".reg .pred P1;\n\t"
                "WAIT_LOOP_%=:\n\t"
                "mbarrier.try_wait.parity.acquire.cta.shared::cta.b64 P1, [%0], %1, 0x989680;\n\t"
                "@P1 bra.uni WAIT_DONE_%=;\n\t"
                "bra.uni WAIT_LOOP_%=;\n\t"
                "WAIT_DONE_%=:\n\t"
                "}"
                :: "r"(mbar), "r"(0u) : "memory");
        }
    }

    // phase 1: local quats from staged sectors
    {
        const float* slot = s_tile + (s * 8 + f) * SLOT_FLOATS;
        const int off = c_OFF[f];
        float v[6];
#pragma unroll
        for (int c = 0; c < 6; ++c)
            v[c] = slot[(j * 6 + c) * 8 + off];
        Quat q = quat_from_6d(v);
        s_lq[f][s][j][0] = q.w; s_lq[f][s][j][1] = q.x;
        s_lq[f][s][j][2] = q.y; s_lq[f][s][j][3] = q.z;
    }
    __syncthreads();

    fk_tail(s_lq, s_gq, s_part, tid, f, s, j, offsets, out);
}

// ---------------------------------------------------------------------------
// Fallback kernel (proven 16.4us LDG path) if tensormap encode is unavailable.
// ---------------------------------------------------------------------------
__global__ void __launch_bounds__(384, 2)
fk_loss_ldg(const float* __restrict__ pred,
            const float* __restrict__ targ,
            const float* __restrict__ offsets,
            float* __restrict__ out)
{
    __shared__ float s_lq[NF][2][NJ][4];
    __shared__ float s_gq[NF][2][NJ][4];
    __shared__ float s_part[12];

    const int tid = threadIdx.x;
    const int b   = blockIdx.x;
    const int f   = tid / 48;
    const int r   = tid - f * 48;
    const int s   = r / NJ;
    const int j   = r - s * NJ;
    const int fi  = c_FIDX[f];

    {
        const float* ptr = s ? targ : pred;
        const float* base = ptr + ((size_t)(b * NJ + j) * 6) * TDIM + fi;
        float v[6];
#pragma unroll
        for (int c = 0; c < 6; ++c)
            v[c] = ld_plain(base + c * TDIM);
        Quat q = quat_from_6d(v);
        s_lq[f][s][j][0] = q.w; s_lq[f][s][j][1] = q.x;
        s_lq[f][s][j][2] = q.y; s_lq[f][s][j][3] = q.z;
    }
    __syncthreads();

    fk_tail(s_lq, s_gq, s_part, tid, f, s, j, offsets, out);
}

// ---------------------------------------------------------------------------
// Host side
// ---------------------------------------------------------------------------
typedef CUresult (*EncodeTiledFn)(
    CUtensorMap*, CUtensorMapDataType, cuuint32_t, void*,
    const cuuint64_t*, const cuuint64_t*, const cuuint32_t*, const cuuint32_t*,
    CUtensorMapInterleave, CUtensorMapSwizzle, CUtensorMapL2promotion,
    CUtensorMapFloatOOBfill);

static bool make_tensormap(EncodeTiledFn enc, CUtensorMap* tm, const float* base) {
    // view: dim0 = t (1024, 4B elems), dim1 = j*6+c (144, stride 4096B),
    //       dim2 = b (256, stride 589824B)
    cuuint64_t dims[3]    = {1024, 144, 256};
    cuuint64_t strides[2] = {4096, 589824};
    cuuint32_t box[3]     = {8, 144, 1};
    cuuint32_t es[3]      = {1, 1, 1};
    CUresult res = enc(tm, CU_TENSOR_MAP_DATA_TYPE_FLOAT32, 3, (void*)base,
                       dims, strides, box, es,
                       CU_TENSOR_MAP_INTERLEAVE_NONE,
                       CU_TENSOR_MAP_SWIZZLE_NONE,
                       CU_TENSOR_MAP_L2_PROMOTION_NONE,
                       CU_TENSOR_MAP_FLOAT_OOB_FILL_NONE);
    return res == CUDA_SUCCESS;
}

// Static host staging for the tensormaps (persists for graph replays).
static __align__(128) CUtensorMap h_tm[2];

extern "C" void kernel_launch(void* const* d_in, const int* in_sizes, int n_in,
                              void* d_out, int out_size) {
    const float* pred    = (const float*)d_in[0];   // (256, 24, 6, 1024)
    const float* targ    = (const float*)d_in[1];   // (256, 24, 6, 1024)
    // d_in[2] = root_translation — cancels in the position diff, never read
    const float* offsets = (const float*)d_in[3];   // (24, 3)
    float* out = (float*)d_out;

    // Resolve cuTensorMapEncodeTiled through the runtime (no -lcuda needed).
    void* fn = nullptr;
    cudaDriverEntryPointQueryResult qr = cudaDriverEntryPointSymbolNotFound;
#if defined(CUDART_VERSION) && (CUDART_VERSION >= 12050)
    cudaGetDriverEntryPointByVersion("cuTensorMapEncodeTiled", &fn, 12000,
                                     cudaEnableDefault, &qr);
#else
    cudaGetDriverEntryPoint("cuTensorMapEncodeTiled", &fn, cudaEnableDefault, &qr);
#endif

    bool use_tma = false;
    if (fn != nullptr && qr == cudaDriverEntryPointSuccess) {
        EncodeTiledFn enc = (EncodeTiledFn)fn;
        use_tma = make_tensormap(enc, &h_tm[0], pred) &&
                  make_tensormap(enc, &h_tm[1], targ);
    }

    if (use_tma) {
        // Stage tensormaps into device-global memory (async copy: capture-legal).
        cudaMemcpyToSymbolAsync(g_tm, h_tm, sizeof(h_tm), 0,
                                cudaMemcpyHostToDevice, 0);
        cudaFuncSetAttribute(fk_loss_tma,
                             cudaFuncAttributeMaxDynamicSharedMemorySize,
                             TILE_BYTES);
        fk_loss_tma<<<NB, 384, TILE_BYTES>>>(offsets, out);
    } else {
        fk_loss_ldg<<<NB, 384>>>(pred, targ, offsets, out);
    }
}

// round 11
// speedup vs baseline: 1.2456x; 1.2456x over previous
#include <cuda_runtime.h>
#include <math.h>

// Problem constants (fixed shapes from setup_inputs)
#define NB 256
#define NJ 24
#define TDIM 1024
#define NF 8
// loss scale: 1 / (B * F * J * 3)
#define LOSS_SCALE (1.0f / 147456.0f)

// Ancestor path (root -> j, inclusive) per joint, padded; LEN = path length.
__device__ __constant__ int c_PATH[NJ][9] = {
    {0,0,0,0,0,0,0,0,0},          // 0
    {0,1,0,0,0,0,0,0,0},          // 1
    {0,2,0,0,0,0,0,0,0},          // 2
    {0,3,0,0,0,0,0,0,0},          // 3
    {0,1,4,0,0,0,0,0,0},          // 4
    {0,2,5,0,0,0,0,0,0},          // 5
    {0,3,6,0,0,0,0,0,0},          // 6
    {0,1,4,7,0,0,0,0,0},          // 7
    {0,2,5,8,0,0,0,0,0},          // 8
    {0,3,6,9,0,0,0,0,0},          // 9
    {0,1,4,7,10,0,0,0,0},         // 10
    {0,2,5,8,11,0,0,0,0},         // 11
    {0,3,6,9,12,0,0,0,0},         // 12
    {0,3,6,9,13,0,0,0,0},         // 13
    {0,3,6,9,14,0,0,0,0},         // 14
    {0,3,6,9,12,15,0,0,0},        // 15
    {0,3,6,9,13,16,0,0,0},        // 16
    {0,3,6,9,14,17,0,0,0},        // 17
    {0,3,6,9,13,16,18,0,0},       // 18
    {0,3,6,9,14,17,19,0,0},       // 19
    {0,3,6,9,13,16,18,20,0},      // 20
    {0,3,6,9,14,17,19,21,0},      // 21
    {0,3,6,9,13,16,18,20,22},     // 22
    {0,3,6,9,14,17,19,21,23}      // 23
};
__device__ __constant__ int c_LEN[NJ] = {
    1,2,2,2,3,3,3,4,4,4,5,5,5,5,5,6,6,6,7,7,8,8,9,9
};
// linspace(0, 1023, 8).astype(int32)
__device__ __constant__ int c_FIDX[NF] = {0,146,292,438,584,730,876,1023};
// Joints whose LOCAL rotation is actually consumed: j appears as a parent in
// PARENTS (positions only read gq[parent]). Leaves {10,11,15,22,23} are dead:
// their local quats feed only their own gq, which nothing consumes.
__device__ __constant__ int c_NEED[NJ] = {
    1,1,1,1, 1,1,1,1, 1,1, 0,0, 1,1,1, 0, 1,1,1,1, 1,1, 0,0
};

// Device-global reduction state (zero-initialized at module load; each launch
// leaves it back at zero -> deterministic across graph replays).
__device__ float        g_acc = 0.0f;
__device__ unsigned int g_cnt = 0u;

struct Quat { float w, x, y, z; };

__device__ __forceinline__ Quat qmul(const Quat a, const Quat b) {
    Quat r;
    r.w = a.w*b.w - a.x*b.x - a.y*b.y - a.z*b.z;
    r.x = a.w*b.x + a.x*b.w + a.y*b.z - a.z*b.y;
    r.y = a.w*b.y - a.x*b.z + a.y*b.w + a.z*b.x;
    r.z = a.w*b.z + a.x*b.y - a.y*b.x + a.z*b.w;
    return r;
}

// rotate v by quaternion q (wxyz):  v + w*t + cross(xyz, t),  t = 2*cross(xyz, v)
__device__ __forceinline__ void qrot(const Quat q, float vx, float vy, float vz,
                                     float& ox, float& oy, float& oz) {
    float tx = 2.0f * (q.y*vz - q.z*vy);
    float ty = 2.0f * (q.z*vx - q.x*vz);
    float tz = 2.0f * (q.x*vy - q.y*vx);
    ox = vx + q.w*tx + (q.y*tz - q.z*ty);
    oy = vy + q.w*ty + (q.z*tx - q.x*tz);
    oz = vz + q.w*tz + (q.x*ty - q.y*tx);
}

// 6d (Zhou et al. Gram-Schmidt) -> rotation matrix -> quaternion (pytorch3d branchless)
__device__ __forceinline__ Quat quat_from_6d(const float v[6]) {
    float a1x = v[0], a1y = v[1], a1z = v[2];
    float a2x = v[3], a2y = v[4], a2z = v[5];
    float n1 = sqrtf(a1x*a1x + a1y*a1y + a1z*a1z);
    float i1 = 1.0f / fmaxf(n1, 1e-8f);
    float b1x = a1x*i1, b1y = a1y*i1, b1z = a1z*i1;
    float d = b1x*a2x + b1y*a2y + b1z*a2z;
    float ux = a2x - d*b1x, uy = a2y - d*b1y, uz = a2z - d*b1z;
    float n2 = sqrtf(ux*ux + uy*uy + uz*uz);
    float i2 = 1.0f / fmaxf(n2, 1e-8f);
    float b2x = ux*i2, b2y = uy*i2, b2z = uz*i2;
    float b3x = b1y*b2z - b1z*b2y;
    float b3y = b1z*b2x - b1x*b2z;
    float b3z = b1x*b2y - b1y*b2x;
    // matrix rows: b1, b2, b3
    float m00 = b1x, m01 = b1y, m02 = b1z;
    float m10 = b2x, m11 = b2y, m12 = b2z;
    float m20 = b3x, m21 = b3y, m22 = b3z;

    float qa0 = sqrtf(fmaxf(1.0f + m00 + m11 + m22, 0.0f));
    float qa1 = sqrtf(fmaxf(1.0f + m00 - m11 - m22, 0.0f));
    float qa2 = sqrtf(fmaxf(1.0f - m00 + m11 - m22, 0.0f));
    float qa3 = sqrtf(fmaxf(1.0f - m00 - m11 + m22, 0.0f));

    // first-argmax semantics (strict >)
    int k = 0; float best = qa0;
    if (qa1 > best) { k = 1; best = qa1; }
    if (qa2 > best) { k = 2; best = qa2; }
    if (qa3 > best) { k = 3; best = qa3; }

    float w, x, y, z, qa;
    if (k == 0) { qa = qa0; w = qa0*qa0;  x = m21 - m12; y = m02 - m20; z = m10 - m01; }
    else if (k == 1) { qa = qa1; w = m21 - m12; x = qa1*qa1;  y = m10 + m01; z = m02 + m20; }
    else if (k == 2) { qa = qa2; w = m02 - m20; x = m10 + m01; y = qa2*qa2;  z = m12 + m21; }
    else             { qa = qa3; w = m10 - m01; x = m20 + m02; y = m21 + m12; z = qa3*qa3;  }

    float inv = 1.0f / (2.0f * fmaxf(qa, 0.1f));
    Quat q; q.w = w*inv; q.x = x*inv; q.y = y*inv; q.z = z*inv;
    return q;
}

// One block per batch b. 384 threads = (f in 0..7) x (side in 0..1) x (joint in 0..23).
//   phase 1: threads whose joint is NEEDED gather 6 scattered scalars -> local quat -> smem
//            (dead-leaf joints {10,11,15,22,23} skipped: -20.8% DRAM traffic)
//   phase 2: needed threads compute global quat via ancestor-path product -> smem
//   phase 3: 192 threads (f, joint) compute squared position diff; block reduce
//   finish:  atomicAdd into device-global accumulator; last block writes out + resets
__global__ void __launch_bounds__(384, 2)
fk_loss_kernel(const float* __restrict__ pred,
               const float* __restrict__ targ,
               const float* __restrict__ offsets,
               float* __restrict__ out) {
    __shared__ float s_lq[NF][2][NJ][4];
    __shared__ float s_gq[NF][2][NJ][4];
    __shared__ float s_part[12];

    const int tid = threadIdx.x;
    const int b   = blockIdx.x;
    const int f   = tid / 48;
    const int r   = tid - f * 48;
    const int s   = r / NJ;          // 0 = pred, 1 = target
    const int j   = r - s * NJ;
    const int fi  = c_FIDX[f];
    const int need = c_NEED[j];

    // ---- phase 1: local quats (only needed joints load: 304 of 384 threads) ----
    if (need) {
        const float* __restrict__ ptr = s ? targ : pred;
        const int base = ((b * NJ + j) * 6) * TDIM + fi;
        float v[6];
#pragma unroll
        for (int c = 0; c < 6; ++c)
            v[c] = __ldg(ptr + base + c * TDIM);
        Quat q = quat_from_6d(v);
        s_lq[f][s][j][0] = q.w; s_lq[f][s][j][1] = q.x;
        s_lq[f][s][j][2] = q.y; s_lq[f][s][j][3] = q.z;
    }
    __syncthreads();

    // ---- phase 2: global quats (left-fold along ancestor path, same FP order as ref)
    //      All joints on any needed path are themselves needed, so smem reads are valid.
    if (need) {
        Quat q = { s_lq[f][s][0][0], s_lq[f][s][0][1], s_lq[f][s][0][2], s_lq[f][s][0][3] };
        const int len = c_LEN[j];
        for (int d2 = 1; d2 < len; ++d2) {
            const int a = c_PATH[j][d2];
            Quat l = { s_lq[f][s][a][0], s_lq[f][s][a][1], s_lq[f][s][a][2], s_lq[f][s][a][3] };
            q = qmul(q, l);
        }
        s_gq[f][s][j][0] = q.w; s_gq[f][s][j][1] = q.x;
        s_gq[f][s][j][2] = q.y; s_gq[f][s][j][3] = q.z;
    }
    __syncthreads();

    // ---- phase 3: position diff (root translation cancels; joint 0 contributes 0)
    //      Only gq of PARENT joints is read (all needed). Leaf positions still computed.
    float acc = 0.0f;
    if (s == 0) {   // 192 threads: one per (f, j)
        float px = 0.f, py = 0.f, pz = 0.f;
        float tx2 = 0.f, ty2 = 0.f, tz2 = 0.f;
        const int len = c_LEN[j];
        for (int d2 = 1; d2 < len; ++d2) {
            const int a = c_PATH[j][d2];
            const int p = c_PATH[j][d2 - 1];
            const float ox = __ldg(offsets + a * 3 + 0);
            const float oy = __ldg(offsets + a * 3 + 1);
            const float oz = __ldg(offsets + a * 3 + 2);
            Quat qp = { s_gq[f][0][p][0], s_gq[f][0][p][1], s_gq[f][0][p][2], s_gq[f][0][p][3] };
            Quat qt = { s_gq[f][1][p][0], s_gq[f][1][p][1], s_gq[f][1][p][2], s_gq[f][1][p][3] };
            float rx, ry, rz;
            qrot(qp, ox, oy, oz, rx, ry, rz);  px  += rx; py  += ry; pz  += rz;
            qrot(qt, ox, oy, oz, rx, ry, rz);  tx2 += rx; ty2 += ry; tz2 += rz;
        }
        const float dx = px - tx2, dy = py - ty2, dz = pz - tz2;
        acc = dx*dx + dy*dy + dz*dz;
    }

    // ---- block reduce: warp shuffle -> smem partials -> thread 0 ----
#pragma unroll
    for (int o = 16; o > 0; o >>= 1)
        acc += __shfl_down_sync(0xffffffffu, acc, o);
    const int wid  = tid >> 5;
    const int lane = tid & 31;
    if (lane == 0) s_part[wid] = acc;
    __syncthreads();

    // ---- grid reduce: device-global accumulator; last block writes + resets ----
    if (tid == 0) {
        float total = 0.0f;
#pragma unroll
        for (int w = 0; w < 12; ++w) total += s_part[w];
        atomicAdd(&g_acc, total);
        __threadfence();
        unsigned int old = atomicAdd(&g_cnt, 1u);
        if (old == NB - 1u) {                 // last block to finish
            __threadfence();
            float tot = *((volatile float*)&g_acc);
            out[0] = tot * LOSS_SCALE;
            // reset for next replay (deterministic state)
            *((volatile float*)&g_acc) = 0.0f;
            __threadfence();
            *((volatile unsigned int*)&g_cnt) = 0u;
        }
    }
}

extern "C" void kernel_launch(void* const* d_in, const int* in_sizes, int n_in,
                              void* d_out, int out_size) {
    const float* pred    = (const float*)d_in[0];   // (256, 24, 6, 1024)
    const float* targ    = (const float*)d_in[1];   // (256, 24, 6, 1024)
    // d_in[2] = root_translation — cancels in the position diff, never read
    const float* offsets = (const float*)d_in[3];   // (24, 3)
    float* out = (float*)d_out;

    fk_loss_kernel<<<NB, 384>>>(pred, targ, offsets, out);
}